// round 2
// baseline (speedup 1.0000x reference)
#include <cuda_runtime.h>
#include <math.h>

#define SEQ  1024
#define NF   256
#define H    1024
#define G4   4096
#define OUTN 1024
#define NB   128   // persistent CTAs (1 per SM, <=148 so all co-resident)
#define JPB  8     // h indices per CTA (NB*JPB == H)

// ---------------- device scratch (static: no allocations allowed) ----------------
__device__ float g_gx[(size_t)SEQ * G4];        // x@W_ih^T + b_ih + b_hh  (16 MB)
__device__ float g_h[(size_t)(SEQ + 1) * H];    // h_0..h_1024             (4 MB)
__device__ float g_logits[(size_t)SEQ * OUTN];  // 4 MB
__device__ float g_lse[SEQ];
__device__ unsigned g_bar[2];                   // [0]=count [1]=phase (memset per launch)

__device__ __forceinline__ float sigm(float x) { return 1.0f / (1.0f + __expf(-x)); }

// ---------------- Kernel A: gx[t][r] = b_ih[r]+b_hh[r] + sum_k X[t][k]*W_ih[r][k] ----
__global__ void precompute_gx(const float* __restrict__ X,
                              const float* __restrict__ Wih,
                              const float* __restrict__ bih,
                              const float* __restrict__ bhh) {
    __shared__ float Xs[32 * NF];                      // 32 KB
    const int r  = blockIdx.x * 256 + threadIdx.x;     // gate row
    const int t0 = blockIdx.y * 32;

    for (int i = threadIdx.x; i < 32 * NF; i += 256)
        Xs[i] = X[(size_t)t0 * NF + i];
    __syncthreads();

    const float bias = bih[r] + bhh[r];
    float acc[32];
#pragma unroll
    for (int tt = 0; tt < 32; tt++) acc[tt] = bias;

    const float4* Wr = (const float4*)(Wih + (size_t)r * NF);
    for (int k4 = 0; k4 < NF / 4; k4++) {
        float4 wv = Wr[k4];
#pragma unroll
        for (int tt = 0; tt < 32; tt++) {
            float4 xv = *(const float4*)&Xs[tt * NF + k4 * 4];   // broadcast LDS
            acc[tt] += wv.x * xv.x + wv.y * xv.y + wv.z * xv.z + wv.w * xv.w;
        }
    }
#pragma unroll
    for (int tt = 0; tt < 32; tt++)
        g_gx[(size_t)(t0 + tt) * G4 + r] = acc[tt];
}

// ---------------- Kernel B: persistent cooperative LSTM recurrence ----------------
// CTA b owns h indices j = b*8..b*8+7. Warp w computes the 4 gate rows of j=b*8+w.
// W_hh rows (32 x 4KB) + W_out rows (8 x 4KB) live in SMEM for the whole kernel.
__global__ void __launch_bounds__(256, 1)
lstm_recurrence(const float* __restrict__ enc,
                const float* __restrict__ Whh,
                const float* __restrict__ Wout,
                const float* __restrict__ bout) {
    extern __shared__ float smem[];
    float* Whh_s  = smem;                  // [8 warps][4 gates][1024]
    float* Wout_s = smem + 8 * 4 * H;      // [8][1024]
    float* hs     = Wout_s + 8 * H;        // [1024]

    const int b = blockIdx.x, tid = threadIdx.x;
    const int w = tid >> 5, l = tid & 31;
    const int j = b * JPB + w;

    // ---- prologue: stage weights into SMEM ----
    for (int rg = 0; rg < 32; rg++) {
        int ww = rg >> 2, g = rg & 3;
        int grow = g * H + b * JPB + ww;
        ((float4*)&Whh_s[(size_t)rg * H])[tid] = ((const float4*)&Whh[(size_t)grow * H])[tid];
    }
    for (int ww = 0; ww < 8; ww++)
        ((float4*)&Wout_s[ww * H])[tid] = ((const float4*)&Wout[(size_t)(b * JPB + ww) * H])[tid];

    const float c0j   = enc[(size_t)(SEQ - 1) * H + j];   // faithful quirk: fixed cell seed
    const float boutj = bout[j];
    if (tid < JPB) g_h[b * JPB + tid] = 0.0f;             // h_0 = 0
    __syncthreads();

    unsigned phase = 0;

    // ---- initial grid barrier (h_0 + gx visible everywhere) ----
    if (tid == 0) {
        __threadfence();
        if (atomicAdd(&g_bar[0], 1) == NB - 1) {
            g_bar[0] = 0;
            __threadfence();
            atomicExch(&g_bar[1], phase + 1);
        }
        while (((volatile unsigned*)g_bar)[1] <= phase) {}
        __threadfence();
    }
    phase++;
    __syncthreads();

    for (int t = 0; t < SEQ; t++) {
        // load h_t into SMEM (and issue gx prefetch early)
        ((float4*)hs)[tid] = ((const float4*)&g_h[(size_t)t * H])[tid];
        float gxv = (l < 4) ? g_gx[(size_t)t * G4 + l * H + j] : 0.0f;
        __syncthreads();

        // ---- phase A: 4 gate dot-products for this warp's j ----
        float hreg[32];
        float a0 = 0.f, a1 = 0.f, a2 = 0.f, a3 = 0.f;
#pragma unroll
        for (int cc = 0; cc < 8; cc++) {
            int c = (cc * 32 + l) * 4;
            float4 hv = *(float4*)&hs[c];
            hreg[cc * 4 + 0] = hv.x; hreg[cc * 4 + 1] = hv.y;
            hreg[cc * 4 + 2] = hv.z; hreg[cc * 4 + 3] = hv.w;
            float4 w0 = *(float4*)&Whh_s[(w * 4 + 0) * H + c];
            float4 w1 = *(float4*)&Whh_s[(w * 4 + 1) * H + c];
            float4 w2 = *(float4*)&Whh_s[(w * 4 + 2) * H + c];
            float4 w3 = *(float4*)&Whh_s[(w * 4 + 3) * H + c];
            a0 += w0.x * hv.x + w0.y * hv.y + w0.z * hv.z + w0.w * hv.w;
            a1 += w1.x * hv.x + w1.y * hv.y + w1.z * hv.z + w1.w * hv.w;
            a2 += w2.x * hv.x + w2.y * hv.y + w2.z * hv.z + w2.w * hv.w;
            a3 += w3.x * hv.x + w3.y * hv.y + w3.z * hv.z + w3.w * hv.w;
        }
#pragma unroll
        for (int off = 16; off; off >>= 1) {
            a0 += __shfl_down_sync(0xffffffffu, a0, off);
            a1 += __shfl_down_sync(0xffffffffu, a1, off);
            a2 += __shfl_down_sync(0xffffffffu, a2, off);
            a3 += __shfl_down_sync(0xffffffffu, a3, off);
        }
        float gx0 = __shfl_sync(0xffffffffu, gxv, 0);
        float gx1 = __shfl_sync(0xffffffffu, gxv, 1);
        float gx2 = __shfl_sync(0xffffffffu, gxv, 2);
        float gx3 = __shfl_sync(0xffffffffu, gxv, 3);
        if (l == 0) {
            float ig = sigm(a0 + gx0);
            float fg = sigm(a1 + gx1);
            float gg = tanhf(a2 + gx2);
            float og = sigm(a3 + gx3);
            float c  = fg * c0j + ig * gg;
            g_h[(size_t)(t + 1) * H + j] = og * tanhf(c);
        }
        __syncthreads();

        // ---- arrive at grid barrier (non-blocking) ----
        if (tid == 0) {
            __threadfence();
            if (atomicAdd(&g_bar[0], 1) == NB - 1) {
                g_bar[0] = 0;
                __threadfence();
                atomicExch(&g_bar[1], phase + 1);
            }
        }

        // ---- phase B (hidden in barrier slack): logits[t-1] from h_t ----
        if (t > 0) {
            float s = 0.f;
#pragma unroll
            for (int cc = 0; cc < 8; cc++) {
                int c = (cc * 32 + l) * 4;
                float4 wv = *(float4*)&Wout_s[w * H + c];
                s += wv.x * hreg[cc * 4 + 0] + wv.y * hreg[cc * 4 + 1]
                   + wv.z * hreg[cc * 4 + 2] + wv.w * hreg[cc * 4 + 3];
            }
#pragma unroll
            for (int off = 16; off; off >>= 1) s += __shfl_down_sync(0xffffffffu, s, off);
            if (l == 0) g_logits[(size_t)(t - 1) * OUTN + j] = s + boutj;
        }

        // ---- wait for barrier ----
        if (tid == 0) {
            while (((volatile unsigned*)g_bar)[1] <= phase) {}
            __threadfence();
        }
        phase++;
        __syncthreads();
    }

    // ---- epilogue: logits[SEQ-1] from h_SEQ ----
    {
        ((float4*)hs)[tid] = ((const float4*)&g_h[(size_t)SEQ * H])[tid];
        __syncthreads();
        float s = 0.f;
#pragma unroll
        for (int cc = 0; cc < 8; cc++) {
            int c = (cc * 32 + l) * 4;
            float4 hv = *(float4*)&hs[c];
            float4 wv = *(float4*)&Wout_s[w * H + c];
            s += wv.x * hv.x + wv.y * hv.y + wv.z * hv.z + wv.w * hv.w;
        }
#pragma unroll
        for (int off = 16; off; off >>= 1) s += __shfl_down_sync(0xffffffffu, s, off);
        if (l == 0) g_logits[(size_t)(SEQ - 1) * OUTN + j] = s + boutj;
    }
}

// ---------------- Kernel C: per-row logsumexp ----------------
__global__ void row_lse() {
    const int t = blockIdx.x, tid = threadIdx.x, w = tid >> 5, l = tid & 31;
    __shared__ float red[8];
    float v[4];
#pragma unroll
    for (int k = 0; k < 4; k++) v[k] = g_logits[(size_t)t * OUTN + tid + k * 256];
    float m = fmaxf(fmaxf(v[0], v[1]), fmaxf(v[2], v[3]));
#pragma unroll
    for (int off = 16; off; off >>= 1) m = fmaxf(m, __shfl_xor_sync(0xffffffffu, m, off));
    if (l == 0) red[w] = m;
    __syncthreads();
    float M = red[0];
#pragma unroll
    for (int i = 1; i < 8; i++) M = fmaxf(M, red[i]);
    float s = 0.f;
#pragma unroll
    for (int k = 0; k < 4; k++) s += expf(v[k] - M);
#pragma unroll
    for (int off = 16; off; off >>= 1) s += __shfl_xor_sync(0xffffffffu, s, off);
    __syncthreads();
    if (l == 0) red[w] = s;
    __syncthreads();
    if (tid == 0) {
        float S = 0.f;
#pragma unroll
        for (int i = 0; i < 8; i++) S += red[i];
        g_lse[t] = M + logf(S);
    }
}

// ---------------- Kernel D: sequential masked-argmax tour selection ----------------
__global__ void tour_select(float* __restrict__ out, int out_size) {
    __shared__ char  vis[OUTN];
    __shared__ float rv[8];
    __shared__ int   ri[8];
    const int tid = threadIdx.x, w = tid >> 5, l = tid & 31;
    for (int i = tid; i < OUTN; i += 256) vis[i] = 0;
    __syncthreads();

    float cur[4];
#pragma unroll
    for (int k = 0; k < 4; k++) cur[k] = g_logits[tid + k * 256];

    for (int t = 0; t < SEQ; t++) {
        float nxt[4];
        if (t + 1 < SEQ) {
#pragma unroll
            for (int k = 0; k < 4; k++)
                nxt[k] = g_logits[(size_t)(t + 1) * OUTN + tid + k * 256];
        }
        float lse_t = g_lse[t];

        float bv = -INFINITY; int bi = 0;
#pragma unroll
        for (int k = 0; k < 4; k++) {
            int c = tid + k * 256;
            float v = vis[c] ? -INFINITY : cur[k];
            if (v > bv) { bv = v; bi = c; }
        }
#pragma unroll
        for (int off = 16; off; off >>= 1) {
            float ov = __shfl_down_sync(0xffffffffu, bv, off);
            int   oi = __shfl_down_sync(0xffffffffu, bi, off);
            if (ov > bv || (ov == bv && oi < bi)) { bv = ov; bi = oi; }
        }
        if (l == 0) { rv[w] = bv; ri[w] = bi; }
        __syncthreads();
        if (tid == 0) {
            float B = rv[0]; int I = ri[0];
#pragma unroll
            for (int i = 1; i < 8; i++)
                if (rv[i] > B || (rv[i] == B && ri[i] < I)) { B = rv[i]; I = ri[i]; }
            if (t < out_size) out[t] = (float)I;                    // tour_idx (exact in fp32)
            if (SEQ + t < out_size) out[SEQ + t] = B - lse_t;       // tour_logp
            vis[I] = 1;
        }
        __syncthreads();
#pragma unroll
        for (int k = 0; k < 4; k++) cur[k] = nxt[k];
    }
}

// ---------------- launch ----------------
extern "C" void kernel_launch(void* const* d_in, const int* in_sizes, int n_in,
                              void* d_out, int out_size) {
    const float* X    = (const float*)d_in[0];
    const float* enc  = (const float*)d_in[1];
    const float* Wih  = (const float*)d_in[2];
    const float* Whh  = (const float*)d_in[3];
    const float* bih  = (const float*)d_in[4];
    const float* bhh  = (const float*)d_in[5];
    const float* Wout = (const float*)d_in[6];
    const float* bout = (const float*)d_in[7];
    float* out = (float*)d_out;

    // reset grid barrier state every launch (graph-capturable memset node)
    void* barAddr = nullptr;
    cudaGetSymbolAddress(&barAddr, g_bar);
    cudaMemsetAsync(barAddr, 0, 2 * sizeof(unsigned));

    size_t smemB = (size_t)(8 * 4 * H + 8 * H + H) * sizeof(float);  // 168 KB
    cudaFuncSetAttribute(lstm_recurrence, cudaFuncAttributeMaxDynamicSharedMemorySize, (int)smemB);

    precompute_gx<<<dim3(16, 32), 256>>>(X, Wih, bih, bhh);
    lstm_recurrence<<<NB, 256, smemB>>>(enc, Whh, Wout, bout);
    row_lse<<<SEQ, 256>>>();
    tour_select<<<1, 256>>>(out, out_size);
}

// round 5
// speedup vs baseline: 1.3862x; 1.3862x over previous
#include <cuda_runtime.h>
#include <math.h>

#define SEQ  1024
#define NF   256
#define H    1024
#define G4   4096
#define OUTN 1024
#define NB   128   // persistent CTAs (1 per SM; all co-resident)
#define JPB  8     // h indices per CTA

// ---------------- device scratch ----------------
__device__ float    g_gx[(size_t)SEQ * G4];        // x@W_ih^T + b_ih + b_hh (16 MB)
__device__ float    g_h[(size_t)(SEQ + 1) * H];    // h_0..h_1024
__device__ float    g_logits[(size_t)SEQ * OUTN];
__device__ float    g_lse[SEQ];
__device__ unsigned g_done[SEQ + 1];               // per-step arrival counters (memset/launch)

__device__ __forceinline__ float sigm(float x) { return 1.0f / (1.0f + __expf(-x)); }

__device__ __forceinline__ unsigned ld_acq(const unsigned* p) {
    unsigned v;
    asm volatile("ld.acquire.gpu.global.u32 %0, [%1];" : "=r"(v) : "l"(p) : "memory");
    return v;
}
__device__ __forceinline__ void red_rel(unsigned* p) {
    asm volatile("red.release.gpu.global.add.u32 [%0], 1;" :: "l"(p) : "memory");
}

// ---------------- Kernel A: gx[t][r] = b_ih[r]+b_hh[r] + X[t]·W_ih[r] ----------------
__global__ void precompute_gx(const float* __restrict__ X,
                              const float* __restrict__ Wih,
                              const float* __restrict__ bih,
                              const float* __restrict__ bhh) {
    __shared__ float Xs[32 * NF];
    const int r  = blockIdx.x * 256 + threadIdx.x;
    const int t0 = blockIdx.y * 32;

    for (int i = threadIdx.x; i < 32 * NF; i += 256)
        Xs[i] = X[(size_t)t0 * NF + i];
    __syncthreads();

    const float bias = bih[r] + bhh[r];
    float acc[32];
#pragma unroll
    for (int tt = 0; tt < 32; tt++) acc[tt] = bias;

    const float4* Wr = (const float4*)(Wih + (size_t)r * NF);
    for (int k4 = 0; k4 < NF / 4; k4++) {
        float4 wv = Wr[k4];
#pragma unroll
        for (int tt = 0; tt < 32; tt++) {
            float4 xv = *(const float4*)&Xs[tt * NF + k4 * 4];
            acc[tt] += wv.x * xv.x + wv.y * xv.y + wv.z * xv.z + wv.w * xv.w;
        }
    }
#pragma unroll
    for (int tt = 0; tt < 32; tt++)
        g_gx[(size_t)(t0 + tt) * G4 + r] = acc[tt];
}

// ---------------- Kernel B: persistent cooperative LSTM recurrence ----------------
__global__ void __launch_bounds__(256, 1)
lstm_recurrence(const float* __restrict__ enc,
                const float* __restrict__ Whh,
                const float* __restrict__ Wout,
                const float* __restrict__ bout) {
    extern __shared__ float smem[];
    float* Whh_s  = smem;               // [32 rows][1024]
    float* Wout_s = smem + 8 * 4 * H;   // [8][1024]
    float* hs     = Wout_s + 8 * H;     // [1024]

    const int b = blockIdx.x, tid = threadIdx.x;
    const int w = tid >> 5, l = tid & 31;
    const int j = b * JPB + w;

    // ---- stage weights ----
    for (int rg = 0; rg < 32; rg++) {
        int ww = rg >> 2, g = rg & 3;
        int grow = g * H + b * JPB + ww;
        ((float4*)&Whh_s[(size_t)rg * H])[tid] = ((const float4*)&Whh[(size_t)grow * H])[tid];
    }
    for (int ww = 0; ww < 8; ww++)
        ((float4*)&Wout_s[ww * H])[tid] = ((const float4*)&Wout[(size_t)(b * JPB + ww) * H])[tid];

    const float c0j   = enc[(size_t)(SEQ - 1) * H + j];
    const float boutj = bout[j];

    float gxv_next = (l < 4) ? g_gx[(size_t)0 * G4 + l * H + j] : 0.0f;  // prefetch t=0
    __syncthreads();

    float hreg[32];

    for (int t = 0; t < SEQ; t++) {
        // ---- wait for h_t (t=0: zeros pre-memset by host) ----
        if (t > 0) {
            if (tid == 0) { while (ld_acq(&g_done[t]) < NB) {} }
            __syncthreads();
        }

        // ---- stage h_t, rotate prefetched gx ----
        ((float4*)hs)[tid] = ((const float4*)&g_h[(size_t)t * H])[tid];
        float gxv = gxv_next;
        __syncthreads();

        // prefetch gx[t+1] (off critical path)
        if (t + 1 < SEQ && l < 4) gxv_next = g_gx[(size_t)(t + 1) * G4 + l * H + j];

        // ---- 4 gate dot-products for this warp's j ----
        float a0 = 0.f, a1 = 0.f, a2 = 0.f, a3 = 0.f;
#pragma unroll
        for (int cc = 0; cc < 8; cc++) {
            int c = (cc * 32 + l) * 4;
            float4 hv = *(float4*)&hs[c];
            hreg[cc * 4 + 0] = hv.x; hreg[cc * 4 + 1] = hv.y;
            hreg[cc * 4 + 2] = hv.z; hreg[cc * 4 + 3] = hv.w;
            float4 w0 = *(float4*)&Whh_s[(w * 4 + 0) * H + c];
            float4 w1 = *(float4*)&Whh_s[(w * 4 + 1) * H + c];
            float4 w2 = *(float4*)&Whh_s[(w * 4 + 2) * H + c];
            float4 w3 = *(float4*)&Whh_s[(w * 4 + 3) * H + c];
            a0 += w0.x * hv.x + w0.y * hv.y + w0.z * hv.z + w0.w * hv.w;
            a1 += w1.x * hv.x + w1.y * hv.y + w1.z * hv.z + w1.w * hv.w;
            a2 += w2.x * hv.x + w2.y * hv.y + w2.z * hv.z + w2.w * hv.w;
            a3 += w3.x * hv.x + w3.y * hv.y + w3.z * hv.z + w3.w * hv.w;
        }
#pragma unroll
        for (int off = 16; off; off >>= 1) {
            a0 += __shfl_down_sync(0xffffffffu, a0, off);
            a1 += __shfl_down_sync(0xffffffffu, a1, off);
            a2 += __shfl_down_sync(0xffffffffu, a2, off);
            a3 += __shfl_down_sync(0xffffffffu, a3, off);
        }
        float gx0 = __shfl_sync(0xffffffffu, gxv, 0);
        float gx1 = __shfl_sync(0xffffffffu, gxv, 1);
        float gx2 = __shfl_sync(0xffffffffu, gxv, 2);
        float gx3 = __shfl_sync(0xffffffffu, gxv, 3);
        if (l == 0) {
            float ig = sigm(a0 + gx0);
            float fg = sigm(a1 + gx1);
            float gg = tanhf(a2 + gx2);
            float og = sigm(a3 + gx3);
            float c  = fg * c0j + ig * gg;
            g_h[(size_t)(t + 1) * H + j] = og * tanhf(c);
        }
        __syncthreads();

        // ---- arrive: fire-and-forget release red (no return trip, no reset, no membar) ----
        if (tid == 0) red_rel(&g_done[t + 1]);

        // ---- hidden in barrier slack: logits[t-1] = h_t · Wout_j ----
        if (t > 0) {
            float s = 0.f;
#pragma unroll
            for (int cc = 0; cc < 8; cc++) {
                int c = (cc * 32 + l) * 4;
                float4 wv = *(float4*)&Wout_s[w * H + c];
                s += wv.x * hreg[cc * 4 + 0] + wv.y * hreg[cc * 4 + 1]
                   + wv.z * hreg[cc * 4 + 2] + wv.w * hreg[cc * 4 + 3];
            }
#pragma unroll
            for (int off = 16; off; off >>= 1) s += __shfl_down_sync(0xffffffffu, s, off);
            if (l == 0) g_logits[(size_t)(t - 1) * OUTN + j] = s + boutj;
        }
    }

    // ---- epilogue: logits[SEQ-1] from h_SEQ ----
    if (tid == 0) { while (ld_acq(&g_done[SEQ]) < NB) {} }
    __syncthreads();
    ((float4*)hs)[tid] = ((const float4*)&g_h[(size_t)SEQ * H])[tid];
    __syncthreads();
    {
        float s = 0.f;
#pragma unroll
        for (int cc = 0; cc < 8; cc++) {
            int c = (cc * 32 + l) * 4;
            float4 hv = *(float4*)&hs[c];
            float4 wv = *(float4*)&Wout_s[w * H + c];
            s += wv.x * hv.x + wv.y * hv.y + wv.z * hv.z + wv.w * hv.w;
        }
#pragma unroll
        for (int off = 16; off; off >>= 1) s += __shfl_down_sync(0xffffffffu, s, off);
        if (l == 0) g_logits[(size_t)(SEQ - 1) * OUTN + j] = s + boutj;
    }
}

// ---------------- Kernel C: per-row logsumexp ----------------
__global__ void row_lse() {
    const int t = blockIdx.x, tid = threadIdx.x, w = tid >> 5, l = tid & 31;
    __shared__ float red[8];
    float v[4];
#pragma unroll
    for (int k = 0; k < 4; k++) v[k] = g_logits[(size_t)t * OUTN + tid + k * 256];
    float m = fmaxf(fmaxf(v[0], v[1]), fmaxf(v[2], v[3]));
#pragma unroll
    for (int off = 16; off; off >>= 1) m = fmaxf(m, __shfl_xor_sync(0xffffffffu, m, off));
    if (l == 0) red[w] = m;
    __syncthreads();
    float M = red[0];
#pragma unroll
    for (int i = 1; i < 8; i++) M = fmaxf(M, red[i]);
    float s = 0.f;
#pragma unroll
    for (int k = 0; k < 4; k++) s += expf(v[k] - M);
#pragma unroll
    for (int off = 16; off; off >>= 1) s += __shfl_xor_sync(0xffffffffu, s, off);
    __syncthreads();
    if (l == 0) red[w] = s;
    __syncthreads();
    if (tid == 0) {
        float S = 0.f;
#pragma unroll
        for (int i = 0; i < 8; i++) S += red[i];
        g_lse[t] = M + logf(S);
    }
}

// ---------------- Kernel D: single-warp bitmask tour selection ----------------
// Lane l owns cities c with ((c>>2)&31)==l; visited mask = one uint32/lane.
// No barriers; next row + lse prefetched one step ahead.
__global__ void tour_select(float* __restrict__ out, int out_size) {
    const int l = threadIdx.x;
    unsigned visMask = 0;

    float4 cur[8], nxt[8];
    const float4* row0 = (const float4*)g_logits;
#pragma unroll
    for (int k = 0; k < 8; k++) cur[k] = row0[k * 32 + l];
    float lse_c = g_lse[0];

    for (int t = 0; t < SEQ; t++) {
        // prefetch next step (independent of this step's work)
        float lse_n = 0.f;
        if (t + 1 < SEQ) {
            const float4* rowN = (const float4*)(g_logits + (size_t)(t + 1) * OUTN);
#pragma unroll
            for (int k = 0; k < 8; k++) nxt[k] = rowN[k * 32 + l];
            lse_n = g_lse[t + 1];
        }

        // local masked argmax over this lane's 32 cities
        float bv = -INFINITY; int bi = 0;
#pragma unroll
        for (int k = 0; k < 8; k++) {
            const float vv[4] = {cur[k].x, cur[k].y, cur[k].z, cur[k].w};
#pragma unroll
            for (int q = 0; q < 4; q++) {
                int bit = k * 4 + q;
                float v = (visMask >> bit) & 1u ? -INFINITY : vv[q];
                int  c  = k * 128 + l * 4 + q;
                if (v > bv) { bv = v; bi = c; }
            }
        }
        // butterfly reduce: every lane ends with the global winner
#pragma unroll
        for (int off = 16; off; off >>= 1) {
            float ov = __shfl_xor_sync(0xffffffffu, bv, off);
            int   oi = __shfl_xor_sync(0xffffffffu, bi, off);
            if (ov > bv || (ov == bv && oi < bi)) { bv = ov; bi = oi; }
        }
        if (l == 0) {
            if (t < out_size)       out[t] = (float)bi;
            if (SEQ + t < out_size) out[SEQ + t] = bv - lse_c;
        }
        // owner lane clears the bit
        if (((bi >> 2) & 31) == l) visMask |= 1u << (((bi >> 7) << 2) | (bi & 3));

#pragma unroll
        for (int k = 0; k < 8; k++) cur[k] = nxt[k];
        lse_c = lse_n;
    }
}

// ---------------- launch ----------------
extern "C" void kernel_launch(void* const* d_in, const int* in_sizes, int n_in,
                              void* d_out, int out_size) {
    const float* X    = (const float*)d_in[0];
    const float* enc  = (const float*)d_in[1];
    const float* Wih  = (const float*)d_in[2];
    const float* Whh  = (const float*)d_in[3];
    const float* bih  = (const float*)d_in[4];
    const float* bhh  = (const float*)d_in[5];
    const float* Wout = (const float*)d_in[6];
    const float* bout = (const float*)d_in[7];
    float* out = (float*)d_out;

    // per-launch resets (graph-capturable async memsets)
    void* doneAddr = nullptr; cudaGetSymbolAddress(&doneAddr, g_done);
    cudaMemsetAsync(doneAddr, 0, (SEQ + 1) * sizeof(unsigned));
    void* hAddr = nullptr; cudaGetSymbolAddress(&hAddr, g_h);
    cudaMemsetAsync(hAddr, 0, H * sizeof(float));   // h_0 = 0

    size_t smemB = (size_t)(8 * 4 * H + 8 * H + H) * sizeof(float);  // 168 KB
    cudaFuncSetAttribute(lstm_recurrence, cudaFuncAttributeMaxDynamicSharedMemorySize, (int)smemB);

    precompute_gx<<<dim3(16, 32), 256>>>(X, Wih, bih, bhh);
    lstm_recurrence<<<NB, 256, smemB>>>(enc, Whh, Wout, bout);
    row_lse<<<SEQ, 256>>>();
    tour_select<<<1, 32>>>(out, out_size);
}